// round 12
// baseline (speedup 1.0000x reference)
#include <cuda_runtime.h>
#include <cuda_bf16.h>

#define NN 16384      // nodes/edges (and bond_n rows A = 16384)
#define DD 128        // emb dim
// Only layer i = 2 matters: the reference loop does not feed h back.

// Scratch (device globals)
__device__ float g_colw4[4][NN];             // 4 deterministic row-slot partials
__device__ float g_hn[(size_t)NN * DD];      // 8 MB
__device__ float g_mpartT[DD][256];          // m partials, contiguous per d
__device__ float g_mm[DD];
__device__ unsigned g_cnt;                   // k_m last-block counter (self-resets)

// ---------------------------------------------------------------------------
// k_stream: pure column-sum, LOW resource (≈40 regs, 4 KB smem) so it
// co-schedules densely on every SM, including those running k_gemm.
// 512 blocks: slice = bid & 127 (128 cols), slot = bid >> 7 (4096 rows).
// Warp loads are 512 B contiguous; per-thread unroll-16 rotating float4 accs.
// ---------------------------------------------------------------------------
__global__ void __launch_bounds__(256) k_stream(const float* __restrict__ bn) {
    __shared__ float part[8][128];
    const int tid  = threadIdx.x;
    const int lane = tid & 31, warp = tid >> 5;
    const int slice = blockIdx.x & 127;
    const int slot  = blockIdx.x >> 7;

    const float* base = bn + (size_t)(slot * 4096 + warp) * NN + slice * 128 + lane * 4;
    float4 a0 = {0,0,0,0}, a1 = {0,0,0,0}, a2 = {0,0,0,0}, a3 = {0,0,0,0};
    for (int i = 0; i < 512; i += 16) {
#pragma unroll
        for (int u = 0; u < 16; u++) {
            float4 v = __ldcs((const float4*)(base + (size_t)(i + u) * 8 * NN));
            float4& a = (u & 3) == 0 ? a0 : (u & 3) == 1 ? a1 : (u & 3) == 2 ? a2 : a3;
            a.x += v.x; a.y += v.y; a.z += v.z; a.w += v.w;
        }
    }
    part[warp][lane * 4 + 0] = a0.x + a1.x + a2.x + a3.x;
    part[warp][lane * 4 + 1] = a0.y + a1.y + a2.y + a3.y;
    part[warp][lane * 4 + 2] = a0.z + a1.z + a2.z + a3.z;
    part[warp][lane * 4 + 3] = a0.w + a1.w + a2.w + a3.w;
    __syncthreads();
    if (tid < 128) {
        float s = 0.f;
#pragma unroll
        for (int w = 0; w < 8; w++) s += part[w][tid];
        g_colw4[slot][slice * 128 + tid] = s;
    }
}

// ---------------------------------------------------------------------------
// k_gemm, 128 blocks: h_n = relu(cat @ Wi_w[2].T + b) -> g_hn. Runs
// CONCURRENTLY with k_stream (separate graph branch, no dependency).
// ---------------------------------------------------------------------------
__global__ void __launch_bounds__(256, 2) k_gemm(
    const int* __restrict__ x, const int* __restrict__ ea,
    const float* __restrict__ aemb, const float* __restrict__ bemb,
    const float* __restrict__ Wi_w2, const float* __restrict__ Wi_b2)
{
    extern __shared__ float sm[];
    float* w_s   = sm;                 // [64][129] = 33,024 B (per-k chunk)
    float* cat_s = sm + 64 * 129;      // [128][64] = 32,768 B
    __shared__ float bias_s[128];
    __shared__ int xi0[128], xi1[128], ei0[128], ei1[128];

    const int tid = threadIdx.x;
    const int rowBase = blockIdx.x * 128;

    if (tid < 128) {
        bias_s[tid] = Wi_b2[tid];
        int r = rowBase + tid;
        xi0[tid] = x[2 * r];  xi1[tid] = x[2 * r + 1];
        ei0[tid] = ea[2 * r]; ei1[tid] = ea[2 * r + 1];
    }
    __syncthreads();

    const int tx = tid & 15, ty = tid >> 4;
    float acc[8][8];
#pragma unroll
    for (int i = 0; i < 8; i++)
#pragma unroll
        for (int j = 0; j < 8; j++) acc[i][j] = 0.f;

    for (int kc = 0; kc < 256; kc += 64) {
        for (int idx = tid; idx < 8192; idx += 256) {
            int d = idx >> 6, kk = idx & 63;
            w_s[kk * 129 + d] = Wi_w2[d * 256 + kc + kk];
        }
        const bool atom = (kc < 128);
        const float* emb = atom ? aemb : bemb;
        for (int idx = tid; idx < 2048; idx += 256) {
            int row  = idx >> 4;
            int kloc = (idx & 15) * 4;
            int i0 = atom ? xi0[row] : ei0[row];
            int i1 = atom ? xi1[row] : ei1[row];
            int ko = atom ? (kc + kloc) : (kc - 128 + kloc);
            float4 v0 = *(const float4*)(emb + i0 * 128 + ko);
            float4 v1 = *(const float4*)(emb + i1 * 128 + ko);
            float4 s;
            s.x = v0.x + v1.x; s.y = v0.y + v1.y;
            s.z = v0.z + v1.z; s.w = v0.w + v1.w;
            *(float4*)(cat_s + row * 64 + kloc) = s;
        }
        __syncthreads();

#pragma unroll 8
        for (int kk = 0; kk < 64; kk++) {
            const float* wr = w_s + kk * 129;
            float b[8], a[8];
#pragma unroll
            for (int j = 0; j < 8; j++) b[j] = wr[tx + 16 * j];
#pragma unroll
            for (int i = 0; i < 8; i++) a[i] = cat_s[(ty + 16 * i) * 64 + kk];
#pragma unroll
            for (int i = 0; i < 8; i++)
#pragma unroll
                for (int j = 0; j < 8; j++)
                    acc[i][j] = fmaf(a[i], b[j], acc[i][j]);
        }
        __syncthreads();
    }

    // bias + relu -> g_hn
#pragma unroll
    for (int i = 0; i < 8; i++) {
        int r = ty + 16 * i;
#pragma unroll
        for (int j = 0; j < 8; j++) {
            int d = tx + 16 * j;
            float v = acc[i][j] + bias_s[d];
            g_hn[(size_t)(rowBase + r) * 128 + d] = v > 0.f ? v : 0.f;
        }
    }
}

// ---------------------------------------------------------------------------
// k_m, 256 blocks: colw = sum of 4 slots; m partial over 64 rows each
// -> g_mpartT[d][b]; last block reduces contiguous partials + mm GEMV.
// ---------------------------------------------------------------------------
__global__ void __launch_bounds__(256) k_m(const float* __restrict__ Wm_w2,
                                           const float* __restrict__ Wm_b2) {
    __shared__ float colw_s[64];
    __shared__ float red[256];
    __shared__ float ms[128];
    __shared__ bool last;

    const int b = blockIdx.x, tid = threadIdx.x;
    const int d = tid & 127, half = tid >> 7;
    const int rowBase = b * 64;

    if (tid < 64) {
        int n = rowBase + tid;
        colw_s[tid] = (g_colw4[0][n] + g_colw4[1][n]) + (g_colw4[2][n] + g_colw4[3][n]);
    }
    __syncthreads();

    {
        float p = 0.f;
#pragma unroll 16
        for (int r = 0; r < 32; r++) {
            int row = half * 32 + r;
            p = fmaf(colw_s[row], g_hn[(size_t)(rowBase + row) * DD + d], p);
        }
        red[tid] = p;
    }
    __syncthreads();
    if (tid < 128) g_mpartT[tid][b] = red[tid] + red[tid + 128];
    __threadfence();
    if (tid == 0) last = (atomicAdd(&g_cnt, 1u) == 255u);
    __syncthreads();

    if (last) {
        if (tid < 128) {
            const float4* mp = (const float4*)g_mpartT[tid];
            float s = 0.f;
#pragma unroll 32
            for (int w = 0; w < 64; w++) {
                float4 v = __ldcg(mp + w);
                s += v.x + v.y + v.z + v.w;
            }
            ms[tid] = s;
        }
        __syncthreads();
        if (tid < 128) {
            float s = Wm_b2[tid];
            const float* row = Wm_w2 + tid * 128;
#pragma unroll 8
            for (int k = 0; k < 128; k++) s = fmaf(ms[k], __ldg(row + k), s);
            g_mm[tid] = s;
        }
        if (tid == 0) g_cnt = 0u;   // reset for next graph replay
    }
}

// ---------------------------------------------------------------------------
// k_out, 2048 blocks: out = relu(h_n + mm[broadcast]).
// ---------------------------------------------------------------------------
__global__ void __launch_bounds__(256) k_out(float* __restrict__ out) {
    __shared__ float mm[128];
    if (threadIdx.x < 128) mm[threadIdx.x] = g_mm[threadIdx.x];
    __syncthreads();
    size_t i = (size_t)blockIdx.x * 256 + threadIdx.x;   // float4 index
    float4 v = *(const float4*)(g_hn + i * 4);
    int d0 = (int)((i * 4) & 127);
    v.x = fmaxf(v.x + mm[d0 + 0], 0.f);
    v.y = fmaxf(v.y + mm[d0 + 1], 0.f);
    v.z = fmaxf(v.z + mm[d0 + 2], 0.f);
    v.w = fmaxf(v.w + mm[d0 + 3], 0.f);
    *((float4*)out + i) = v;
}

// ---------------------------------------------------------------------------
extern "C" void kernel_launch(void* const* d_in, const int* in_sizes, int n_in,
                              void* d_out, int out_size) {
    const int*   x    = (const int*)d_in[0];
    const int*   ea   = (const int*)d_in[1];
    const float* bn   = (const float*)d_in[2];
    const float* aemb = (const float*)d_in[3];
    const float* bemb = (const float*)d_in[4];
    const float* Wi_w = (const float*)d_in[5];
    const float* Wi_b = (const float*)d_in[6];
    const float* Wm_w = (const float*)d_in[7];
    const float* Wm_b = (const float*)d_in[8];

    // Only the last layer (i = 2) affects the output.
    const float* Wi_w2 = Wi_w + 2 * 128 * 256;
    const float* Wi_b2 = Wi_b + 2 * 128;
    const float* Wm_w2 = Wm_w + 2 * 128 * 128;
    const float* Wm_b2 = Wm_b + 2 * 128;

    const int smem = (64 * 129 + 128 * 64) * (int)sizeof(float);  // 65,792 B

    // Lazily create side stream + fork/join events ONCE (host-side objects;
    // no device memory). Standard graph-capture fork-join pattern.
    static cudaStream_t s2 = nullptr;
    static cudaEvent_t evFork = nullptr, evJoin = nullptr;
    if (s2 == nullptr) {
        cudaStreamCreateWithFlags(&s2, cudaStreamNonBlocking);
        cudaEventCreateWithFlags(&evFork, cudaEventDisableTiming);
        cudaEventCreateWithFlags(&evJoin, cudaEventDisableTiming);
        cudaFuncSetAttribute(k_gemm, cudaFuncAttributeMaxDynamicSharedMemorySize, smem);
    }

    // Fork: k_stream runs on s2 CONCURRENTLY with k_gemm on the main stream.
    cudaEventRecord(evFork, 0);
    cudaStreamWaitEvent(s2, evFork, 0);
    k_stream<<<512, 256, 0, s2>>>(bn);
    k_gemm<<<128, 256, smem>>>(x, ea, aemb, bemb, Wi_w2, Wi_b2);
    // Join both branches back into the main stream.
    cudaEventRecord(evJoin, s2);
    cudaStreamWaitEvent(0, evJoin, 0);

    k_m<<<256, 256>>>(Wm_w2, Wm_b2);
    k_out<<<2048, 256>>>((float*)d_out);
}

// round 13
// speedup vs baseline: 1.3107x; 1.3107x over previous
#include <cuda_runtime.h>
#include <cuda_bf16.h>

#define NN 16384      // nodes/edges (and bond_n rows A = 16384)
#define DD 128        // emb dim
// Only layer i = 2 matters: the reference loop does not feed h back.

// Scratch (device globals — zero-initialized at module load)
__device__ float g_colw[NN];
__device__ float g_hn[(size_t)NN * DD];      // 8 MB
__device__ float g_mpartT[DD][256];          // m partials, contiguous per d
__device__ float g_mm[DD];
__device__ unsigned g_cnt;                   // k_m last-block counter (self-resets)

// ---------------------------------------------------------------------------
// k_fused (R2 structure, the session's wall-clock best): 256 blocks.
//   blocks [0,128):   column-sum of bond_n. Block b owns columns
//                     [b*128, b*128+128) over ALL 16384 rows -> g_colw
//                     (direct write, no atomics, no partials).
//   blocks [128,256): GEMM h_n = relu(cat @ Wi_w[2].T + b), 128 rows each.
// ---------------------------------------------------------------------------
__global__ void __launch_bounds__(256) k_fused(
    const float* __restrict__ bn,
    const int* __restrict__ x, const int* __restrict__ ea,
    const float* __restrict__ aemb, const float* __restrict__ bemb,
    const float* __restrict__ Wi_w2, const float* __restrict__ Wi_b2)
{
    extern __shared__ float sm[];
    const int tid = threadIdx.x;
    const int bid = blockIdx.x;

    if (bid < 128) {
        // ---------------- column-sum path ----------------
        const int lane = tid & 31, warp = tid >> 5;
        // each thread: 4 columns, rows warp, warp+8, ... (2048 rows)
        const float* base = bn + (size_t)warp * NN + bid * 128 + lane * 4;
        float4 a0 = {0,0,0,0}, a1 = {0,0,0,0}, a2 = {0,0,0,0}, a3 = {0,0,0,0};
        for (int i = 0; i < 2048; i += 16) {
#pragma unroll
            for (int u = 0; u < 16; u++) {
                float4 v = __ldcs((const float4*)(base + (size_t)(i + u) * 8 * NN));
                float4& a = (u & 3) == 0 ? a0 : (u & 3) == 1 ? a1 : (u & 3) == 2 ? a2 : a3;
                a.x += v.x; a.y += v.y; a.z += v.z; a.w += v.w;
            }
        }
        float sx = a0.x + a1.x + a2.x + a3.x;
        float sy = a0.y + a1.y + a2.y + a3.y;
        float sz = a0.z + a1.z + a2.z + a3.z;
        float sw = a0.w + a1.w + a2.w + a3.w;
        // cross-warp reduce: part[8][128]
        float* part = sm;
        part[warp * 128 + lane * 4 + 0] = sx;
        part[warp * 128 + lane * 4 + 1] = sy;
        part[warp * 128 + lane * 4 + 2] = sz;
        part[warp * 128 + lane * 4 + 3] = sw;
        __syncthreads();
        if (tid < 128) {
            float s = 0.f;
#pragma unroll
            for (int w = 0; w < 8; w++) s += part[w * 128 + tid];
            g_colw[bid * 128 + tid] = s;
        }
        return;
    }

    // ---------------- GEMM path ----------------
    float* w_s   = sm;                 // [64][129]  = 33,024 B (per-k chunk)
    float* cat_s = sm + 64 * 129;      // [128][64]  = 32,768 B

    __shared__ float bias_s[128];
    __shared__ int xi0[128], xi1[128], ei0[128], ei1[128];

    const int rowBase = (bid - 128) * 128;

    if (tid < 128) {
        bias_s[tid] = Wi_b2[tid];
        int r = rowBase + tid;
        xi0[tid] = x[2 * r];  xi1[tid] = x[2 * r + 1];
        ei0[tid] = ea[2 * r]; ei1[tid] = ea[2 * r + 1];
    }
    __syncthreads();

    const int tx = tid & 15, ty = tid >> 4;
    float acc[8][8];
#pragma unroll
    for (int i = 0; i < 8; i++)
#pragma unroll
        for (int j = 0; j < 8; j++) acc[i][j] = 0.f;

    for (int kc = 0; kc < 256; kc += 64) {
        // stage W chunk transposed: w_s[kk][d] = Wi_w2[d*256 + kc + kk]
        for (int idx = tid; idx < 8192; idx += 256) {
            int d = idx >> 6, kk = idx & 63;
            w_s[kk * 129 + d] = Wi_w2[d * 256 + kc + kk];
        }
        // stage cat chunk: cat_s[row][kloc] (embedding pair-sum gathers)
        const bool atom = (kc < 128);
        const float* emb = atom ? aemb : bemb;
        for (int idx = tid; idx < 2048; idx += 256) {
            int row  = idx >> 4;
            int kloc = (idx & 15) * 4;
            int i0 = atom ? xi0[row] : ei0[row];
            int i1 = atom ? xi1[row] : ei1[row];
            int ko = atom ? (kc + kloc) : (kc - 128 + kloc);
            float4 v0 = *(const float4*)(emb + i0 * 128 + ko);
            float4 v1 = *(const float4*)(emb + i1 * 128 + ko);
            float4 s;
            s.x = v0.x + v1.x; s.y = v0.y + v1.y;
            s.z = v0.z + v1.z; s.w = v0.w + v1.w;
            *(float4*)(cat_s + row * 64 + kloc) = s;
        }
        __syncthreads();

#pragma unroll 8
        for (int kk = 0; kk < 64; kk++) {
            const float* wr = w_s + kk * 129;
            float b[8], a[8];
#pragma unroll
            for (int j = 0; j < 8; j++) b[j] = wr[tx + 16 * j];
#pragma unroll
            for (int i = 0; i < 8; i++) a[i] = cat_s[(ty + 16 * i) * 64 + kk];
#pragma unroll
            for (int i = 0; i < 8; i++)
#pragma unroll
                for (int j = 0; j < 8; j++)
                    acc[i][j] = fmaf(a[i], b[j], acc[i][j]);
        }
        __syncthreads();
    }

    // epilogue: bias + relu -> g_hn
#pragma unroll
    for (int i = 0; i < 8; i++) {
        int r = ty + 16 * i;
#pragma unroll
        for (int j = 0; j < 8; j++) {
            int d = tx + 16 * j;
            float v = acc[i][j] + bias_s[d];
            g_hn[(size_t)(rowBase + r) * 128 + d] = v > 0.f ? v : 0.f;
        }
    }
}

// ---------------------------------------------------------------------------
// k_m (lean version — the session's one isolated proven win):
// 256 blocks, each owns 64 rows. m partial (unroll 16) -> g_mpartT[d][b]
// (transposed: contiguous per d). Last block: 64 consecutive float4 loads
// per d to reduce the 256 partials, then mm = m @ Wm^T + b. Counter resets.
// ---------------------------------------------------------------------------
__global__ void __launch_bounds__(256) k_m(const float* __restrict__ Wm_w2,
                                           const float* __restrict__ Wm_b2) {
    __shared__ float colw_s[64];
    __shared__ float red[256];
    __shared__ float ms[128];
    __shared__ bool last;

    const int b = blockIdx.x, tid = threadIdx.x;
    const int d = tid & 127, half = tid >> 7;
    const int rowBase = b * 64;

    if (tid < 64) colw_s[tid] = g_colw[rowBase + tid];
    __syncthreads();

    // m partial: rows [rowBase + half*32, +32)
    {
        float p = 0.f;
#pragma unroll 16
        for (int r = 0; r < 32; r++) {
            int row = half * 32 + r;
            p = fmaf(colw_s[row], g_hn[(size_t)(rowBase + row) * DD + d], p);
        }
        red[tid] = p;
    }
    __syncthreads();
    if (tid < 128) g_mpartT[tid][b] = red[tid] + red[tid + 128];
    __threadfence();
    if (tid == 0) last = (atomicAdd(&g_cnt, 1u) == 255u);
    __syncthreads();

    if (last) {
        if (tid < 128) {
            const float4* mp = (const float4*)g_mpartT[tid];
            float s = 0.f;
#pragma unroll 32
            for (int w = 0; w < 64; w++) {
                float4 v = __ldcg(mp + w);
                s += v.x + v.y + v.z + v.w;
            }
            ms[tid] = s;
        }
        __syncthreads();
        if (tid < 128) {
            float s = Wm_b2[tid];
            const float* row = Wm_w2 + tid * 128;
#pragma unroll 8
            for (int k = 0; k < 128; k++) s = fmaf(ms[k], __ldg(row + k), s);
            g_mm[tid] = s;
        }
        if (tid == 0) g_cnt = 0u;   // reset for next graph replay
    }
}

// ---------------------------------------------------------------------------
// k_out, 2048 blocks: out = relu(h_n + mm[broadcast])
// ---------------------------------------------------------------------------
__global__ void __launch_bounds__(256) k_out(float* __restrict__ out) {
    __shared__ float mm[128];
    if (threadIdx.x < 128) mm[threadIdx.x] = g_mm[threadIdx.x];
    __syncthreads();
    size_t i = (size_t)blockIdx.x * 256 + threadIdx.x;   // float4 index
    float4 v = *(const float4*)(g_hn + i * 4);
    int d0 = (int)((i * 4) & 127);
    v.x = fmaxf(v.x + mm[d0 + 0], 0.f);
    v.y = fmaxf(v.y + mm[d0 + 1], 0.f);
    v.z = fmaxf(v.z + mm[d0 + 2], 0.f);
    v.w = fmaxf(v.w + mm[d0 + 3], 0.f);
    *((float4*)out + i) = v;
}

// ---------------------------------------------------------------------------
extern "C" void kernel_launch(void* const* d_in, const int* in_sizes, int n_in,
                              void* d_out, int out_size) {
    const int*   x    = (const int*)d_in[0];
    const int*   ea   = (const int*)d_in[1];
    const float* bn   = (const float*)d_in[2];
    const float* aemb = (const float*)d_in[3];
    const float* bemb = (const float*)d_in[4];
    const float* Wi_w = (const float*)d_in[5];
    const float* Wi_b = (const float*)d_in[6];
    const float* Wm_w = (const float*)d_in[7];
    const float* Wm_b = (const float*)d_in[8];

    // Only the last layer (i = 2) affects the output.
    const float* Wi_w2 = Wi_w + 2 * 128 * 256;
    const float* Wi_b2 = Wi_b + 2 * 128;
    const float* Wm_w2 = Wm_w + 2 * 128 * 128;
    const float* Wm_b2 = Wm_b + 2 * 128;

    const int smem = (64 * 129 + 128 * 64) * (int)sizeof(float);  // 65,792 B
    static bool attr_set = false;
    if (!attr_set) {
        cudaFuncSetAttribute(k_fused, cudaFuncAttributeMaxDynamicSharedMemorySize, smem);
        attr_set = true;
    }

    k_fused<<<256, 256, smem>>>(bn, x, ea, aemb, bemb, Wi_w2, Wi_b2);
    k_m<<<256, 256>>>(Wm_w2, Wm_b2);
    k_out<<<2048, 256>>>((float*)d_out);
}